// round 10
// baseline (speedup 1.0000x reference)
#include <cuda_runtime.h>
#include <stdint.h>
#include <math.h>

// HighPassFilter: order-2 IIR biquad, 256 sequences of T=65536 float32.
// R10 = R9 pipeline (CHUNK=256, cp.async distance-2, 3-buffer ring, guarded
// prefetch) with WARM 96->64. R8's post-mortem proved R2's WARM=64 "failure"
// was actually an unguarded OOB prefetch (identical rel_err 2.830794e-03 in
// both rounds), so WARM=64 was never falsified. Pole decay 0.823^64 ~ 3.7e-6,
// calibrated estimate ~3e-5 << 1e-3. NT 11->10, read amplification 1.375->1.25.

#define T_LEN   65536
#define CHUNK   256     // samples per lane
#define WARM    64      // warm-up samples (re-testing; R2 failure was OOB bug)
#define JT      32      // j-tile width
#define NT      ((CHUNK + WARM) / JT)   // 10 tiles per warp
#define NBUF    3       // SMEM ring depth (prefetch distance 2)
#define BLOCK_WARPS 2
#define ROWSTRIDE 36    // 32 + 4 pad; 16B accesses at 144B stride: conflict-free

#define ROWBYTES  (ROWSTRIDE * 4)       // 144
#define BUFBYTES  (32 * ROWBYTES)       // 4608

__device__ __forceinline__ void cp_async16(uint32_t dst_smem, const float* src, int src_size)
{
    asm volatile("cp.async.cg.shared.global [%0], [%1], 16, %2;\n"
                 :: "r"(dst_smem), "l"(src), "r"(src_size));
}

__global__ __launch_bounds__(BLOCK_WARPS * 32, 1)
void biquad_hp_kernel(const float* __restrict__ x, float* __restrict__ y,
                      float b0, float b1, float b2, float na1, float na2)
{
    // 3-deep ring of transpose tiles per warp
    __shared__ __align__(16) float tile[BLOCK_WARPS][NBUF][32][ROWSTRIDE];

    const int w    = threadIdx.x >> 5;
    const int lane = threadIdx.x & 31;
    const int g    = lane >> 3;   // chunk subgroup (0..3)
    const int m    = lane & 7;    // float4 slot within 32-sample tile (0..7)

    // 8 warps per sequence, each warp owns 32 contiguous chunks = 8192 samples
    const int gw   = blockIdx.x * BLOCK_WARPS + w;
    const int seq  = gw >> 3;
    const int wseq = gw & 7;

    const long long seqbase = (long long)seq * T_LEN;
    const float* xs = x + seqbase;
    float*       ys = y + seqbase;
    const int warpbase = wseq * (32 * CHUNK);
    const int slotbase = warpbase + g * CHUNK + 4 * m;

    // SMEM byte addresses of this lane's cp.async destination, per ring slot.
    // it-step "it" targets row c = it*4+g, float offset 4m:
    //   byte = it*(4*ROWBYTES) + g*ROWBYTES + 16*m
    uint32_t smem_dst[NBUF];
    {
        uint32_t base;
        asm("{ .reg .u64 t; cvta.to.shared.u64 t, %1; cvt.u32.u64 %0, t; }"
            : "=r"(base) : "l"(&tile[w][0][0][0]));
        const uint32_t off = (uint32_t)g * ROWBYTES + (uint32_t)m * 16;
        #pragma unroll
        for (int b = 0; b < NBUF; ++b)
            smem_dst[b] = base + (uint32_t)b * BUFBYTES + off;
    }
    const uint32_t rowstep = 4 * ROWBYTES;   // 576 bytes per it-step

    float xm1 = 0.f, xm2 = 0.f, ym1 = 0.f, ym2 = 0.f;

    // ---- prologue: prefetch tiles 0 and 1 (separate commit groups)
    #pragma unroll
    for (int pt = 0; pt < 2; ++pt) {
        const int jt = -WARM + pt * JT;
        #pragma unroll
        for (int it = 0; it < 8; ++it) {
            int p = slotbase + it * (4 * CHUNK) + jt;
            cp_async16(smem_dst[pt] + it * rowstep,
                       xs + (p >= 0 ? p : 0), p >= 0 ? 16 : 0);
        }
        asm volatile("cp.async.commit_group;\n");
    }

    #pragma unroll
    for (int t = 0; t < NT; ++t) {
        const int  jt   = -WARM + t * JT;
        const bool emit = (jt >= 0);
        float (*buf)[ROWSTRIDE] = tile[w][t % NBUF];
        float* row = buf[lane];

        // ---- issue tile t+2's cp.async (distance-2 lead), GUARDED against
        //      pre-sequence reads; always commit a group so
        //      "all but 2 newest complete" == "tile t complete".
        if (t + 2 < NT) {
            const int jn = jt + 2 * JT;
            #pragma unroll
            for (int it = 0; it < 8; ++it) {
                int p = slotbase + it * (4 * CHUNK) + jn;
                cp_async16(smem_dst[(t + 2) % NBUF] + it * rowstep,
                           xs + (p >= 0 ? p : 0), p >= 0 ? 16 : 0);
            }
        }
        asm volatile("cp.async.commit_group;\n");
        asm volatile("cp.async.wait_group 2;\n");   // tile t's data landed
        __syncwarp();

        // ---- advance this lane's chunk 32 samples (serial IIR chain)
        #pragma unroll
        for (int jj = 0; jj < JT; jj += 4) {
            float4 xv = *reinterpret_cast<float4*>(&row[jj]);

            float t0 = fmaf(b2, xm2, fmaf(b1, xm1, b0 * xv.x));
            float y0 = fmaf(na2, ym2, fmaf(na1, ym1, t0));
            float t1 = fmaf(b2, xm1, fmaf(b1, xv.x, b0 * xv.y));
            float y1 = fmaf(na2, ym1, fmaf(na1, y0, t1));
            float t2 = fmaf(b2, xv.x, fmaf(b1, xv.y, b0 * xv.z));
            float y2 = fmaf(na2, y0, fmaf(na1, y1, t2));
            float t3 = fmaf(b2, xv.y, fmaf(b1, xv.z, b0 * xv.w));
            float y3 = fmaf(na2, y1, fmaf(na1, y2, t3));

            xm2 = xv.z; xm1 = xv.w;
            ym2 = y2;   ym1 = y3;

            if (emit)
                *reinterpret_cast<float4*>(&row[jj]) =
                    make_float4(y0, y1, y2, y3);
        }
        __syncwarp();

        // ---- coalesced store of computed tile (in-place transposed SMEM)
        if (emit) {
            #pragma unroll
            for (int it = 0; it < 8; ++it) {
                int c = it * 4 + g;
                int p = slotbase + it * (4 * CHUNK) + jt;
                *reinterpret_cast<float4*>(ys + p) =
                    *reinterpret_cast<const float4*>(&buf[c][4 * m]);
            }
        }
        __syncwarp();
    }
}

extern "C" void kernel_launch(void* const* d_in, const int* in_sizes, int n_in,
                              void* d_out, int out_size)
{
    const float* x = (const float*)d_in[0];
    float*       y = (float*)d_out;

    const int total = in_sizes[0];
    const int nseq  = total / T_LEN;          // 256 for the given shapes

    const double w0    = 2.0 * M_PI * (700.0 / 16000.0);
    const double cw    = cos(w0);
    const double sw    = sin(w0);
    const double q     = 0.70710678;
    const double alpha = sw / (2.0 * q);
    const double a0    = 1.0 + alpha;

    const float b0 = (float)(((1.0 + cw) / 2.0) / a0);
    const float b1 = (float)((-(1.0 + cw)) / a0);
    const float b2 = b0;
    const float a1 = (float)((-2.0 * cw) / a0);
    const float a2 = (float)((1.0 - alpha) / a0);

    const int warps_total = nseq * 8;                  // 8 warps per sequence
    const int grid        = warps_total / BLOCK_WARPS; // 1024 blocks
    biquad_hp_kernel<<<grid, BLOCK_WARPS * 32>>>(x, y, b0, b1, b2, -a1, -a2);
}

// round 11
// speedup vs baseline: 1.2675x; 1.2675x over previous
#include <cuda_runtime.h>
#include <stdint.h>
#include <math.h>

// HighPassFilter: order-2 IIR biquad, 256 sequences of T=65536 float32.
// R11 = R9 (CHUNK=256, WARM=96, cp.async distance-2, 3-buffer ring) with the
// SMEM layout fixed: ROWSTRIDE 36->32 plus XOR swizzle (quad q of row r at
// physical quad q^(r&7)). The old 144B-row layout had a 4-way bank conflict
// on the store-side LDS.128 AND the cp.async SMEM-write path (64B lane stride
// within each 8-lane phase) -- conflicted async writes delayed group
// completion, which is why issue% stayed ~25% at every prefetch depth.

#define T_LEN   65536
#define CHUNK   256     // samples per lane (validated)
#define WARM    96      // warm-up samples (validated)
#define JT      32      // j-tile width
#define NT      ((CHUNK + WARM) / JT)   // 11 tiles per warp
#define NBUF    3       // SMEM ring depth (prefetch distance 2)
#define BLOCK_WARPS 2
#define ROWSTRIDE 32    // exact 128B rows; swizzle provides conflict-freedom

#define ROWBYTES  (ROWSTRIDE * 4)       // 128
#define BUFBYTES  (32 * ROWBYTES)       // 4096

__device__ __forceinline__ void cp_async16(uint32_t dst_smem, const float* src, int src_size)
{
    asm volatile("cp.async.cg.shared.global [%0], [%1], 16, %2;\n"
                 :: "r"(dst_smem), "l"(src), "r"(src_size));
}

__global__ __launch_bounds__(BLOCK_WARPS * 32, 1)
void biquad_hp_kernel(const float* __restrict__ x, float* __restrict__ y,
                      float b0, float b1, float b2, float na1, float na2)
{
    // 3-deep ring of swizzled transpose tiles per warp
    __shared__ __align__(16) float tile[BLOCK_WARPS][NBUF][32][ROWSTRIDE];

    const int w    = threadIdx.x >> 5;
    const int lane = threadIdx.x & 31;
    const int g    = lane >> 3;   // chunk subgroup (0..3)
    const int m    = lane & 7;    // 16B slot within a 32-sample tile row (0..7)

    // 8 warps per sequence, each warp owns 32 contiguous chunks = 8192 samples
    const int gw   = blockIdx.x * BLOCK_WARPS + w;
    const int seq  = gw >> 3;
    const int wseq = gw & 7;

    const long long seqbase = (long long)seq * T_LEN;
    const float* xs = x + seqbase;
    float*       ys = y + seqbase;
    const int warpbase = wseq * (32 * CHUNK);
    const int slotbase = warpbase + g * CHUNK + 4 * m;

    // cp.async dst: row r=4it+g, logical quad m -> physical quad m^(r&7).
    // byte = r*128 + ((m^g)*16 ^ (it&1 ? 64 : 0))  [4it mod 8 = 4(it&1)]
    uint32_t ringbase;
    {
        asm("{ .reg .u64 t; cvta.to.shared.u64 t, %1; cvt.u32.u64 %0, t; }"
            : "=r"(ringbase) : "l"(&tile[w][0][0][0]));
    }
    const uint32_t off0 = (uint32_t)g * 128u + (uint32_t)((m ^ g) << 4);
    const uint32_t off1 = off0 ^ 64u;

    // store/read side float index within a buffer, per it:
    //   (4it+g)*32 + ((m^g)*4 ^ (it&1 ? 16 : 0))
    const int sidx0 = g * 32 + ((m ^ g) << 2);
    const int sidx1 = sidx0 ^ 16;

    float xm1 = 0.f, xm2 = 0.f, ym1 = 0.f, ym2 = 0.f;

    // ---- prologue: prefetch tiles 0 and 1 (separate commit groups)
    #pragma unroll
    for (int pt = 0; pt < 2; ++pt) {
        const int jt = -WARM + pt * JT;
        const uint32_t dbase = ringbase + (uint32_t)pt * BUFBYTES;
        #pragma unroll
        for (int it = 0; it < 8; ++it) {
            int p = slotbase + it * (4 * CHUNK) + jt;
            uint32_t d = dbase + (uint32_t)(it << 9) + ((it & 1) ? off1 : off0);
            cp_async16(d, xs + (p >= 0 ? p : 0), p >= 0 ? 16 : 0);
        }
        asm volatile("cp.async.commit_group;\n");
    }

    #pragma unroll
    for (int t = 0; t < NT; ++t) {
        const int  jt   = -WARM + t * JT;
        const bool emit = (jt >= 0);
        float* buf = &tile[w][t % NBUF][0][0];
        float* row = buf + lane * ROWSTRIDE;
        const int lq = lane & 7;   // swizzle key for compute-side access

        // ---- issue tile t+2's cp.async (distance-2 lead), guarded against
        //      pre-sequence reads; always commit a group so
        //      "all but 2 newest complete" == "tile t complete".
        if (t + 2 < NT) {
            const int jn = jt + 2 * JT;
            const uint32_t dbase = ringbase + (uint32_t)((t + 2) % NBUF) * BUFBYTES;
            #pragma unroll
            for (int it = 0; it < 8; ++it) {
                int p = slotbase + it * (4 * CHUNK) + jn;
                uint32_t d = dbase + (uint32_t)(it << 9) + ((it & 1) ? off1 : off0);
                cp_async16(d, xs + (p >= 0 ? p : 0), p >= 0 ? 16 : 0);
            }
        }
        asm volatile("cp.async.commit_group;\n");
        asm volatile("cp.async.wait_group 2;\n");   // tile t's data landed
        __syncwarp();

        // ---- advance this lane's chunk 32 samples (serial IIR chain);
        //      logical quad j at physical quad j^(lane&7)
        #pragma unroll
        for (int jj = 0; jj < JT; jj += 4) {
            const int colq = ((jj >> 2) ^ lq) << 2;
            float4 xv = *reinterpret_cast<float4*>(&row[colq]);

            float t0 = fmaf(b2, xm2, fmaf(b1, xm1, b0 * xv.x));
            float y0 = fmaf(na2, ym2, fmaf(na1, ym1, t0));
            float t1 = fmaf(b2, xm1, fmaf(b1, xv.x, b0 * xv.y));
            float y1 = fmaf(na2, ym1, fmaf(na1, y0, t1));
            float t2 = fmaf(b2, xv.x, fmaf(b1, xv.y, b0 * xv.z));
            float y2 = fmaf(na2, y0, fmaf(na1, y1, t2));
            float t3 = fmaf(b2, xv.y, fmaf(b1, xv.z, b0 * xv.w));
            float y3 = fmaf(na2, y1, fmaf(na1, y2, t3));

            xm2 = xv.z; xm1 = xv.w;
            ym2 = y2;   ym1 = y3;

            if (emit)
                *reinterpret_cast<float4*>(&row[colq]) =
                    make_float4(y0, y1, y2, y3);
        }
        __syncwarp();

        // ---- coalesced store of computed tile (swizzled SMEM read)
        if (emit) {
            #pragma unroll
            for (int it = 0; it < 8; ++it) {
                int p = slotbase + it * (4 * CHUNK) + jt;
                const int si = it * 128 + ((it & 1) ? sidx1 : sidx0);
                *reinterpret_cast<float4*>(ys + p) =
                    *reinterpret_cast<const float4*>(buf + si);
            }
        }
        __syncwarp();
    }
}

extern "C" void kernel_launch(void* const* d_in, const int* in_sizes, int n_in,
                              void* d_out, int out_size)
{
    const float* x = (const float*)d_in[0];
    float*       y = (float*)d_out;

    const int total = in_sizes[0];
    const int nseq  = total / T_LEN;          // 256 for the given shapes

    const double w0    = 2.0 * M_PI * (700.0 / 16000.0);
    const double cw    = cos(w0);
    const double sw    = sin(w0);
    const double q     = 0.70710678;
    const double alpha = sw / (2.0 * q);
    const double a0    = 1.0 + alpha;

    const float b0 = (float)(((1.0 + cw) / 2.0) / a0);
    const float b1 = (float)((-(1.0 + cw)) / a0);
    const float b2 = b0;
    const float a1 = (float)((-2.0 * cw) / a0);
    const float a2 = (float)((1.0 - alpha) / a0);

    const int warps_total = nseq * 8;                  // 8 warps per sequence
    const int grid        = warps_total / BLOCK_WARPS; // 1024 blocks
    biquad_hp_kernel<<<grid, BLOCK_WARPS * 32>>>(x, y, b0, b1, b2, -a1, -a2);
}